// round 10
// baseline (speedup 1.0000x reference)
#include <cuda_runtime.h>
#include <cuda_bf16.h>
#include <cstdint>

// Problem constants
#define NB   32
#define CIN  256
#define COUT 256
#define H    56
#define W    56
#define HW   3136
#define HB   58   // padded rows (0..57)
#define WB   66   // padded cols (0..65)

// bf16 encodings of sign values
#define BF_P1 0x3F80
#define BF_M1 0xBF80

// conv staging: stage covers 64 ci: A = 128px x 128B, B = 128co x 128B
#define STG_A   16384
#define STG_SZ  32768
#define SMEM_MBAR_OFF 1024
#define SMEM_BUF_OFF 2048
#define SMEM_TOTAL   (2048 + 3 * STG_SZ)   // 100352

// prep kernel block ranges
#define ZB_BLOCKS 2768
#define WBK_BLOCKS 2304
#define AB_BLOCKS 28672
#define PREP_BLOCKS (ZB_BLOCKS + WBK_BLOCKS + AB_BLOCKS)

// Scratch (bf16 sign values)
__device__ __align__(1024) uint16_t g_act[(size_t)NB * HB * WB * CIN];
__device__ __align__(1024) uint16_t g_wb[9 * COUT * CIN];

__device__ __forceinline__ uint16_t bsign(float v) {
    return (v > 0.f) ? (uint16_t)BF_P1 : ((v < 0.f) ? (uint16_t)BF_M1 : (uint16_t)0);
}

__device__ __forceinline__ uint32_t su32(const void* p) {
    return (uint32_t)__cvta_generic_to_shared(p);
}

#define CP16(dst, src) \
    asm volatile("cp.async.cg.shared.global [%0], [%1], 16;\n" :: "r"(dst), "l"(src))
// Arrive on mbarrier when all of this thread's prior cp.asyncs have completed.
#define CPASYNC_MBAR_ARRIVE(mbar) \
    asm volatile("cp.async.mbarrier.arrive.noinc.shared.b64 [%0];" \
                 :: "r"((uint32_t)(mbar)) : "memory")
#define MBARRIER_INIT(mbar, cnt) \
    asm volatile("mbarrier.init.shared.b64 [%0], %1;" \
                 :: "r"((uint32_t)(mbar)), "r"((uint32_t)(cnt)) : "memory")
#define MBARRIER_ARRIVE(mbar) \
    asm volatile("mbarrier.arrive.shared.b64 _, [%0];" \
                 :: "r"((uint32_t)(mbar)) : "memory")
#define MBAR_WAIT(mbar, parity) do {                                          \
    uint32_t _m = (uint32_t)(mbar);                                           \
    uint32_t _p = (uint32_t)(parity);                                         \
    asm volatile(                                                             \
        "{\n\t.reg .pred P1;\n\t"                                             \
        "WAIT_LOOP_%=:\n\t"                                                   \
        "mbarrier.try_wait.parity.shared.b64 P1, [%0], %1, 0x989680;\n\t"     \
        "@P1 bra.uni WAIT_DONE_%=;\n\t"                                       \
        "bra.uni WAIT_LOOP_%=;\n\t"                                           \
        "WAIT_DONE_%=:\n\t}"                                                  \
        :: "r"(_m), "r"(_p) : "memory");                                      \
} while (0)

__device__ __forceinline__ void ldsm_x4(uint32_t* r, uint32_t addr) {
    asm volatile("ldmatrix.sync.aligned.m8n8.x4.shared.b16 {%0,%1,%2,%3}, [%4];"
                 : "=r"(r[0]), "=r"(r[1]), "=r"(r[2]), "=r"(r[3]) : "r"(addr));
}
__device__ __forceinline__ void mma_bf16(float* d, const uint32_t* a, const uint32_t* b) {
    asm volatile(
        "mma.sync.aligned.m16n8k16.row.col.f32.bf16.bf16.f32 "
        "{%0,%1,%2,%3}, {%4,%5,%6,%7}, {%8,%9}, {%0,%1,%2,%3};\n"
        : "+f"(d[0]), "+f"(d[1]), "+f"(d[2]), "+f"(d[3])
        : "r"(a[0]), "r"(a[1]), "r"(a[2]), "r"(a[3]), "r"(b[0]), "r"(b[1]));
}

// ---------------------------------------------------------------------------
// Fused prep: zero borders | binarize weights | binarize+transpose acts.
// ---------------------------------------------------------------------------
__global__ void prep_kernel(const float* __restrict__ x, const float* __restrict__ M) {
    __shared__ uint16_t t[32][33];
    int b = blockIdx.x;
    int tid = threadIdx.x;

    if (b < ZB_BLOCKS) {
        int idx = b * 256 + tid;
        int word = idx & 31;
        int bp   = (idx >> 5) % 692;
        int n    = idx / (692 * 32);
        int yy, xx;
        if (bp < 66)       { yy = 0;  xx = bp; }
        else if (bp < 132) { yy = 57; xx = bp - 66; }
        else {
            int r = bp - 132;
            yy = 1 + r / 10;
            int c = r % 10;
            xx = (c == 0) ? 0 : (56 + c);
        }
        float4* p = reinterpret_cast<float4*>(g_act);
        p[((size_t)(n * HB + yy) * WB + xx) * 32 + word] =
            make_float4(0.f, 0.f, 0.f, 0.f);
    } else if (b < ZB_BLOCKS + WBK_BLOCKS) {
        int o = (b - ZB_BLOCKS) * 256 + tid;
        int tap = o >> 16;
        int co  = (o >> 8) & 255;
        int ci  = o & 255;
        g_wb[o] = bsign(M[(size_t)(co * CIN + ci) * 9 + tap]);
    } else {
        int bb = b - (ZB_BLOCKS + WBK_BLOCKS);
        int xt = bb & 1;
        int cg = (bb >> 1) & 7;
        int nz = bb >> 4;
        int n = nz / H, y = nz % H;
        int x0 = xt * 32;
        int c0 = cg * 32;
        int tx = tid & 31, ty = tid >> 5;

        #pragma unroll
        for (int i = 0; i < 4; i++) {
            int ci = c0 + ty + i * 8;
            int xx = x0 + tx;
            float v = 0.f;
            if (xx < W)
                v = x[(((size_t)n * CIN + ci) * H + y) * W + xx];
            t[ty + i * 8][tx] = bsign(v);
        }
        __syncthreads();
        int pxi = tid >> 4;
        int cp  = tid & 15;
        #pragma unroll
        for (int j = 0; j < 2; j++) {
            int xl = pxi + j * 16;
            int xx = x0 + xl;
            if (xx < W) {
                uint32_t v = (uint32_t)t[cp * 2][xl] |
                             ((uint32_t)t[cp * 2 + 1][xl] << 16);
                uint32_t* dst = reinterpret_cast<uint32_t*>(
                    g_act + (((size_t)n * HB + (y + 1)) * WB + (xx + 1)) * CIN + c0);
                dst[cp] = v;
            }
        }
    }
}

// ---------------------------------------------------------------------------
// bf16 implicit-GEMM conv, mbarrier full/empty pipeline (no per-stage
// __syncthreads). CTA: 128 px x 128 co; K = 36 stages of 64 ci; 3 buffers.
// full[b]: 256 arrivals via cp.async.mbarrier.arrive.noinc (producer done)
// empty[b]: 256 arrivals via mbarrier.arrive (consumers done reading)
// ---------------------------------------------------------------------------
__global__ void __launch_bounds__(256, 2)
conv_mma_kernel(const float* __restrict__ alpha, float* __restrict__ out) {
    extern __shared__ char smem[];
    uint32_t sb = su32(smem);
    float* alphaS = (float*)smem;                 // 512B
    float* epi    = (float*)(smem + SMEM_BUF_OFF); // aliases buffers (post-loop)

    int tid  = threadIdx.x;
    int wid  = tid >> 5, lane = tid & 31;
    int p0   = blockIdx.x * 128;
    int n    = blockIdx.y;
    int co0  = blockIdx.z * 128;

    // mbarriers: full[b] at +b*16, empty[b] at +b*16+8
    uint32_t mb = sb + SMEM_MBAR_OFF;
    if (tid == 0) {
        #pragma unroll
        for (int b = 0; b < 3; b++) {
            MBARRIER_INIT(mb + b * 16, 256);      // full
            MBARRIER_INIT(mb + b * 16 + 8, 256);  // empty
        }
    }
    if (tid < 128) alphaS[tid] = alpha[co0 + tid];
    __syncthreads();

    // ---- producer constants ----
    int pc = tid & 7;            // 16B chunk within 128B row (8 ci each)
    int pr = tid >> 3;           // smem row 0..31 (rows pr+32i)
    uint32_t pdst = (uint32_t)(pr * 128) + (uint32_t)(((pc ^ (pr & 7)) << 4));
    size_t aoff[4];
    #pragma unroll
    for (int i = 0; i < 4; i++) {
        int p = p0 + pr + 32 * i;
        if (p > HW - 1) p = HW - 1;   // clamp tail tile
        int yy = p / W, xx = p - yy * W;
        aoff[i] = ((size_t)(n * HB + yy) * WB + xx) * CIN + pc * 8;
    }
    const uint16_t* gbBase = g_wb + (size_t)(co0 + pr) * CIN + pc * 8;

    // produce stage p (0..35): wait empty, fill buffer p%3, arrive full.
    auto produce = [&](int p) {
        if (p < 36) {
            int buf = p % 3;
            int pj  = p / 3;
            MBAR_WAIT(mb + buf * 16 + 8, (pj + 1) & 1);   // wait empty
            int tap = p >> 2, q = p & 3;
            int kh = tap / 3, kw = tap - kh * 3;
            int tapoff = (kh * WB + kw) * CIN + q * 64;
            const uint16_t* gb = gbBase + ((size_t)tap * (COUT * CIN) + q * 64);
            uint32_t base = sb + SMEM_BUF_OFF + (uint32_t)(buf * STG_SZ);
            uint32_t ad = base + pdst;
            uint32_t bd = base + STG_A + pdst;
            #pragma unroll
            for (int i = 0; i < 4; i++)
                CP16(ad + i * 4096, g_act + aoff[i] + tapoff);
            #pragma unroll
            for (int i = 0; i < 4; i++)
                CP16(bd + i * 4096, gb + (size_t)i * (32 * CIN));
            CPASYNC_MBAR_ARRIVE(mb + buf * 16);           // arrive full (async)
        }
    };

    produce(0);
    produce(1);
    produce(2);

    // ---- consumer constants ----
    int mw = wid & 1;            // px half (64 px)
    int nw = wid >> 1;           // co quarter (32 co)
    int rlA = (lane & 7) + ((lane >> 3) & 1) * 8;
    int hiA = lane >> 4;
    int swA = rlA & 7;
    int rlB = (lane & 7) + ((lane >> 4) & 1) * 8;
    int hiB = (lane >> 3) & 1;
    int swB = rlB & 7;

    float acc[4][4][4];
    #pragma unroll
    for (int mt = 0; mt < 4; mt++)
        #pragma unroll
        for (int nt = 0; nt < 4; nt++)
            #pragma unroll
            for (int c = 0; c < 4; c++) acc[mt][nt][c] = 0.f;

    #pragma unroll 3
    for (int s = 0; s < 36; s++) {
        int buf = s % 3;
        int j   = s / 3;
        MBAR_WAIT(mb + buf * 16, j & 1);        // wait full[buf]

        uint32_t aB = sb + SMEM_BUF_OFF + (uint32_t)(buf * STG_SZ);
        uint32_t bB = aB + STG_A;
        #pragma unroll
        for (int kc = 0; kc < 4; kc++) {
            uint32_t a[4][4], b2[2][4];
            #pragma unroll
            for (int mt = 0; mt < 4; mt++) {
                uint32_t addr = aB + (uint32_t)((mw * 64 + mt * 16 + rlA) * 128)
                              + (uint32_t)((((kc * 2 + hiA) ^ swA) << 4));
                ldsm_x4(a[mt], addr);
            }
            #pragma unroll
            for (int np = 0; np < 2; np++) {
                int row = nw * 32 + np * 16 + rlB;
                uint32_t addr = bB + (uint32_t)(row * 128)
                              + (uint32_t)((((kc * 2 + hiB) ^ swB) << 4));
                ldsm_x4(b2[np], addr);
            }
            #pragma unroll
            for (int mt = 0; mt < 4; mt++)
                #pragma unroll
                for (int nt = 0; nt < 4; nt++)
                    mma_bf16(acc[mt][nt], a[mt], &b2[nt >> 1][(nt & 1) * 2]);
        }
        MBARRIER_ARRIVE(mb + buf * 16 + 8);     // release buffer
        produce(s + 3);                          // refill (off critical head)
    }

    // ---- epilogue: transpose through smem (aliases buffers), scale, store
    __syncthreads();   // everyone past all buffer reads before alias reuse
    #pragma unroll
    for (int mt = 0; mt < 4; mt++) {
        int px = mw * 64 + mt * 16 + (lane >> 2);
        #pragma unroll
        for (int nt = 0; nt < 4; nt++) {
            int co = nw * 32 + nt * 8 + 2 * (lane & 3);
            epi[co * 132 + px]           = acc[mt][nt][0];
            epi[(co + 1) * 132 + px]     = acc[mt][nt][1];
            epi[co * 132 + px + 8]       = acc[mt][nt][2];
            epi[(co + 1) * 132 + px + 8] = acc[mt][nt][3];
        }
    }
    __syncthreads();

    #pragma unroll 4
    for (int r = wid; r < 512; r += 8) {
        int co = r >> 2;
        int pl = (r & 3) * 32 + lane;       // local px 0..127
        int p  = p0 + pl;
        if (p < HW) {
            float v = epi[co * 132 + pl] * alphaS[co];
            out[((size_t)n * COUT + co0 + co) * HW + p] = v;
        }
    }
}

// ---------------------------------------------------------------------------
extern "C" void kernel_launch(void* const* d_in, const int* in_sizes, int n_in,
                              void* d_out, int out_size) {
    const float* x     = (const float*)d_in[0];
    const float* M     = (const float*)d_in[1];
    const float* alpha = (const float*)d_in[2];
    float* out = (float*)d_out;

    prep_kernel<<<PREP_BLOCKS, 256>>>(x, M);

    cudaFuncSetAttribute(conv_mma_kernel,
                         cudaFuncAttributeMaxDynamicSharedMemorySize, SMEM_TOTAL);
    dim3 grid(25, NB, 2);
    conv_mma_kernel<<<grid, 256, SMEM_TOTAL>>>(alpha, out);
}

// round 12
// speedup vs baseline: 1.4269x; 1.4269x over previous
#include <cuda_runtime.h>
#include <cuda_bf16.h>
#include <cstdint>

// Problem constants
#define NB   32
#define CIN  256
#define COUT 256
#define H    56
#define W    56
#define HW   3136
#define HB   58   // padded rows (0..57)
#define WB   66   // padded cols (0..65)

// bf16 encodings of sign values
#define BF_P1 0x3F80u
#define BF_M1 0xBF80u

// conv staging: stage covers 64 ci: A = 128px x 128B, B = 128co x 128B
#define STG_A   16384
#define STG_SZ  32768
#define NSTAGE  3
#define SMEM_EPI_OFF 1024
#define SMEM_BUF_OFF 1024
#define SMEM_TOTAL   (1024 + NSTAGE * STG_SZ)   // 99328

// Scratch (bf16 sign values)
__device__ __align__(1024) uint16_t g_act[(size_t)NB * HB * WB * CIN];
__device__ __align__(1024) uint16_t g_wb[9 * COUT * CIN];

__device__ __forceinline__ uint16_t bsign(float v) {
    return (v > 0.f) ? (uint16_t)BF_P1 : ((v < 0.f) ? (uint16_t)BF_M1 : (uint16_t)0);
}

__device__ __forceinline__ uint32_t su32(const void* p) {
    return (uint32_t)__cvta_generic_to_shared(p);
}

#define CP16(dst, src) \
    asm volatile("cp.async.cg.shared.global [%0], [%1], 16;\n" :: "r"(dst), "l"(src))
#define CP_COMMIT() asm volatile("cp.async.commit_group;\n" ::: "memory")
#define CP_WAIT1()  asm volatile("cp.async.wait_group 1;\n" ::: "memory")

__device__ __forceinline__ void ldsm_x4(uint32_t* r, uint32_t addr) {
    asm volatile("ldmatrix.sync.aligned.m8n8.x4.shared.b16 {%0,%1,%2,%3}, [%4];"
                 : "=r"(r[0]), "=r"(r[1]), "=r"(r[2]), "=r"(r[3]) : "r"(addr));
}
__device__ __forceinline__ void mma_bf16(float* d, const uint32_t* a, const uint32_t* b) {
    asm volatile(
        "mma.sync.aligned.m16n8k16.row.col.f32.bf16.bf16.f32 "
        "{%0,%1,%2,%3}, {%4,%5,%6,%7}, {%8,%9}, {%0,%1,%2,%3};\n"
        : "+f"(d[0]), "+f"(d[1]), "+f"(d[2]), "+f"(d[3])
        : "r"(a[0]), "r"(a[1]), "r"(a[2]), "r"(a[3]), "r"(b[0]), "r"(b[1]));
}

// ---------------------------------------------------------------------------
// Zero padded borders of g_act.
// ---------------------------------------------------------------------------
__global__ void zero_border_kernel() {
    int idx = blockIdx.x * 256 + threadIdx.x;
    const int total = NB * 692 * 32;
    if (idx >= total) return;
    int word = idx & 31;
    int bp   = (idx >> 5) % 692;
    int n    = idx / (692 * 32);
    int yy, xx;
    if (bp < 66)       { yy = 0;  xx = bp; }
    else if (bp < 132) { yy = 57; xx = bp - 66; }
    else {
        int r = bp - 132;
        yy = 1 + r / 10;
        int c = r % 10;
        xx = (c == 0) ? 0 : (56 + c);
    }
    float4* p = reinterpret_cast<float4*>(g_act);
    p[((size_t)(n * HB + yy) * WB + xx) * 32 + word] = make_float4(0.f, 0.f, 0.f, 0.f);
}

// ---------------------------------------------------------------------------
// Binarize + transpose x: NCHW fp32 -> padded NHWC bf16 (interior only).
// Vectorized: float4 reads (4 consecutive x), STG.64 writes (4 ci).
// Row stride 34 u16 = 68B so vector u32 shared stores stay 4B-aligned.
// Grid (2, 8, NB*H), block 256 flat.
// ---------------------------------------------------------------------------
__global__ void bin_act_kernel(const float* __restrict__ x) {
    __shared__ uint16_t t[32][34];
    int nz = blockIdx.z;
    int n = nz / H, y = nz % H;
    int x0 = blockIdx.x * 32;
    int c0 = blockIdx.y * 32;
    int tid = threadIdx.x;

    // read phase: r = local ci (0..31), cxi = x quad (0..7), x = x0 + cxi*4
    int r   = tid >> 3;
    int cxi = tid & 7;
    int xloc = cxi * 4;
    if (x0 + xloc < W) {                 // x0=32: cxi<6 (covers x 32..55)
        const float4* src = reinterpret_cast<const float4*>(
            x + (((size_t)n * CIN + c0 + r) * H + y) * W + x0 + xloc);
        float4 v = *src;
        uint32_t p0 = (uint32_t)bsign(v.x) | ((uint32_t)bsign(v.y) << 16);
        uint32_t p1 = (uint32_t)bsign(v.z) | ((uint32_t)bsign(v.w) << 16);
        // row stride 68B (mult of 4), xloc even -> 4B-aligned u32 stores
        uint32_t* dst = reinterpret_cast<uint32_t*>(&t[r][xloc]);
        dst[0] = p0;
        dst[1] = p1;
    }
    __syncthreads();

    // write phase: px = tid>>3 (0..31), ch = tid&7 -> 4 ci per STG.64
    int px = tid >> 3;
    int ch = tid & 7;
    if (x0 + px < W) {
        uint16_t s0 = t[ch * 4 + 0][px];
        uint16_t s1 = t[ch * 4 + 1][px];
        uint16_t s2 = t[ch * 4 + 2][px];
        uint16_t s3 = t[ch * 4 + 3][px];
        uint64_t v = (uint64_t)s0 | ((uint64_t)s1 << 16) |
                     ((uint64_t)s2 << 32) | ((uint64_t)s3 << 48);
        uint64_t* dst = reinterpret_cast<uint64_t*>(
            g_act + (((size_t)n * HB + (y + 1)) * WB + (x0 + px + 1)) * CIN + c0);
        dst[ch] = v;
    }
}

// ---------------------------------------------------------------------------
// Binarize weights: OIHW fp32 -> [tap][co][ci] bf16.
// ---------------------------------------------------------------------------
__global__ void bin_w_kernel(const float* __restrict__ M) {
    int o = blockIdx.x * 256 + threadIdx.x;
    int tap = o >> 16;
    int co  = (o >> 8) & 255;
    int ci  = o & 255;
    g_wb[o] = bsign(M[(size_t)(co * CIN + ci) * 9 + tap]);
}

// ---------------------------------------------------------------------------
// bf16 implicit-GEMM conv, linear-pixel tiling (R7 structure).
// CTA: 128 consecutive pixels x 128 co; K = 9*256 in 36 stages of 64 ci;
// 3-buffer cp.async pipeline; produce() placed inside kc0's ldsm latency window.
// ---------------------------------------------------------------------------
__global__ void __launch_bounds__(256, 2)
conv_mma_kernel(const float* __restrict__ alpha, float* __restrict__ out) {
    extern __shared__ char smem[];
    uint32_t sb = su32(smem);
    float* alphaS = (float*)smem;                 // 512B
    float* epi    = (float*)(smem + SMEM_EPI_OFF);

    int tid  = threadIdx.x;
    int wid  = tid >> 5, lane = tid & 31;
    int p0   = blockIdx.x * 128;
    int n    = blockIdx.y;
    int co0  = blockIdx.z * 128;

    if (tid < 128) alphaS[tid] = alpha[co0 + tid];

    // ---- producer constants ----
    int pc = tid & 7;            // 16B chunk within 128B row (8 ci each)
    int pr = tid >> 3;           // smem row 0..31 (rows pr+32i)
    uint32_t pdst = (uint32_t)(pr * 128) + (uint32_t)(((pc ^ (pr & 7)) << 4));
    size_t aoff[4];
    #pragma unroll
    for (int i = 0; i < 4; i++) {
        int p = p0 + pr + 32 * i;
        if (p > HW - 1) p = HW - 1;   // clamp tail tile
        int yy = p / W, xx = p - yy * W;
        aoff[i] = ((size_t)(n * HB + yy) * WB + xx) * CIN + pc * 8;
    }
    const uint16_t* gbBase = g_wb + (size_t)(co0 + pr) * CIN + pc * 8;

    auto produce = [&](int s) {
        if (s < 36) {
            int tap = s >> 2, q = s & 3;        // 64-ci quarter
            int kh = tap / 3, kw = tap - kh * 3;
            int tapoff = (kh * WB + kw) * CIN + q * 64;
            const uint16_t* gb = gbBase + ((size_t)tap * (COUT * CIN) + q * 64);
            uint32_t base = sb + SMEM_BUF_OFF + (uint32_t)((s % 3) * STG_SZ);
            uint32_t ad = base + pdst;
            uint32_t bd = base + STG_A + pdst;
            #pragma unroll
            for (int i = 0; i < 4; i++)
                CP16(ad + i * 4096, g_act + aoff[i] + tapoff);
            #pragma unroll
            for (int i = 0; i < 4; i++)
                CP16(bd + i * 4096, gb + (size_t)i * (32 * CIN));
        }
        CP_COMMIT();
    };

    produce(0);
    produce(1);

    // ---- consumer constants ----
    int mw = wid & 1;            // px half (64 px)
    int nw = wid >> 1;           // co quarter (32 co)
    int rlA = (lane & 7) + ((lane >> 3) & 1) * 8;
    int hiA = lane >> 4;
    int swA = rlA & 7;
    int rlB = (lane & 7) + ((lane >> 4) & 1) * 8;
    int hiB = (lane >> 3) & 1;
    int swB = rlB & 7;

    float acc[4][4][4];
    #pragma unroll
    for (int mt = 0; mt < 4; mt++)
        #pragma unroll
        for (int nt = 0; nt < 4; nt++)
            #pragma unroll
            for (int c = 0; c < 4; c++) acc[mt][nt][c] = 0.f;

    for (int s = 0; s < 36; s++) {
        CP_WAIT1();
        __syncthreads();           // stage s resident; all warps done with s-1

        uint32_t aB = sb + SMEM_BUF_OFF + (uint32_t)((s % 3) * STG_SZ);
        uint32_t bB = aB + STG_A;

        uint32_t a[4][4], b2[2][4];
        // kc=0 fragment loads, then produce so the LDGSTS burst fills
        // the ldsm->mma latency window.
        #pragma unroll
        for (int mt = 0; mt < 4; mt++) {
            uint32_t addr = aB + (uint32_t)((mw * 64 + mt * 16 + rlA) * 128)
                          + (uint32_t)(((hiA ^ swA) << 4));
            ldsm_x4(a[mt], addr);
        }
        #pragma unroll
        for (int np = 0; np < 2; np++) {
            int row = nw * 32 + np * 16 + rlB;
            uint32_t addr = bB + (uint32_t)(row * 128)
                          + (uint32_t)(((hiB ^ swB) << 4));
            ldsm_x4(b2[np], addr);
        }

        produce(s + 2);            // refill buf (s+2)%3 == (s-1)%3

        #pragma unroll
        for (int kc = 0; kc < 4; kc++) {
            #pragma unroll
            for (int mt = 0; mt < 4; mt++)
                #pragma unroll
                for (int nt = 0; nt < 4; nt++)
                    mma_bf16(acc[mt][nt], a[mt], &b2[nt >> 1][(nt & 1) * 2]);
            if (kc < 3) {
                #pragma unroll
                for (int mt = 0; mt < 4; mt++) {
                    uint32_t addr = aB + (uint32_t)((mw * 64 + mt * 16 + rlA) * 128)
                                  + (uint32_t)(((((kc + 1) * 2 + hiA) ^ swA) << 4));
                    ldsm_x4(a[mt], addr);
                }
                #pragma unroll
                for (int np = 0; np < 2; np++) {
                    int row = nw * 32 + np * 16 + rlB;
                    uint32_t addr = bB + (uint32_t)(row * 128)
                                  + (uint32_t)(((((kc + 1) * 2 + hiB) ^ swB) << 4));
                    ldsm_x4(b2[np], addr);
                }
            }
        }
    }

    // ---- epilogue: transpose through smem, scale by alpha, coalesced stores
    __syncthreads();
    #pragma unroll
    for (int mt = 0; mt < 4; mt++) {
        int px = mw * 64 + mt * 16 + (lane >> 2);
        #pragma unroll
        for (int nt = 0; nt < 4; nt++) {
            int co = nw * 32 + nt * 8 + 2 * (lane & 3);
            epi[co * 132 + px]           = acc[mt][nt][0];
            epi[(co + 1) * 132 + px]     = acc[mt][nt][1];
            epi[co * 132 + px + 8]       = acc[mt][nt][2];
            epi[(co + 1) * 132 + px + 8] = acc[mt][nt][3];
        }
    }
    __syncthreads();

    #pragma unroll 4
    for (int r = wid; r < 512; r += 8) {
        int co = r >> 2;
        int pl = (r & 3) * 32 + lane;       // local px 0..127
        int p  = p0 + pl;
        if (p < HW) {
            float v = epi[co * 132 + pl] * alphaS[co];
            out[((size_t)n * COUT + co0 + co) * HW + p] = v;
        }
    }
}

// ---------------------------------------------------------------------------
extern "C" void kernel_launch(void* const* d_in, const int* in_sizes, int n_in,
                              void* d_out, int out_size) {
    const float* x     = (const float*)d_in[0];
    const float* M     = (const float*)d_in[1];
    const float* alpha = (const float*)d_in[2];
    float* out = (float*)d_out;

    {
        int total = NB * 692 * 32;
        zero_border_kernel<<<(total + 255) / 256, 256>>>();
    }
    {
        dim3 grid(2, 8, NB * H);
        bin_act_kernel<<<grid, 256>>>(x);
    }
    bin_w_kernel<<<(9 * COUT * CIN) / 256, 256>>>(M);

    cudaFuncSetAttribute(conv_mma_kernel,
                         cudaFuncAttributeMaxDynamicSharedMemorySize, SMEM_TOTAL);
    dim3 grid(25, NB, 2);
    conv_mma_kernel<<<grid, 256, SMEM_TOTAL>>>(alpha, out);
}